// round 8
// baseline (speedup 1.0000x reference)
#include <cuda_runtime.h>
#include <math.h>
#include <cstdint>

// ---------------------------------------------------------------------------
// FastConvLSTM restructured + tf32 mma.sync recurrence (baseline-PTX only —
// the harness compiles via compute_103, so no tcgen05/arch-'a' features):
//   enc  = relu((x @ W1c)*bn_s + b1)                 [B*T, 64] (tf32-rounded)
//   pre_i = enc @ Qi ;  pre_f = enc @ Qf + h[0:512] @ Wf
//   pre_o = h[512:1280] @ Wo ;  pre_g = h[1280:2048] @ Wg
//   c = sig(pre_f)*c + sig(pre_i)*tanh(pre_g); h = sig(pre_o)*tanh(c)
// Step kernel: CTA = 64x64 tile, 4 warps (2x2), mma.sync m16n8k8 tf32,
// cp.async double-buffered K-chunks of 32, fused LSTM epilogue.
// ---------------------------------------------------------------------------

#define BATCH 2048
#define TSTEPS 128
#define FEAT 84
#define BT (BATCH * TSTEPS)

__device__ __align__(128) float g_W1[FEAT * 64];
__device__ __align__(128) float g_b1[64];
__device__ __align__(128) float g_S[1024 * 64];          // S[o][c]
__device__ __align__(128) float g_QT[4096 * 64];         // [j][k]  j: [0,2048)=i, [2048,4096)=f
__device__ __align__(128) float g_bias_if[4096];
__device__ __align__(128) float g_WfT[2048 * 512];       // [j][k]
__device__ __align__(128) float g_WoT[2048 * 768];
__device__ __align__(128) float g_WgT[2048 * 768];
__device__ __align__(128) float g_bias_o[2048];
__device__ __align__(128) float g_bias_g[2048];
__device__ __align__(128) float g_enc[(size_t)BT * 64];
__device__ __align__(128) float g_h[2][(size_t)BATCH * 2048];
__device__ __align__(128) float g_c[(size_t)BATCH * 2048];
__device__ __align__(128) float g_hid[(size_t)BATCH * 128];

// ---------------- helpers ----------------

__device__ __forceinline__ uint32_t smem_u32(const void* p) {
    uint32_t a;
    asm("{ .reg .u64 t; cvta.to.shared.u64 t, %1; cvt.u32.u64 %0, t; }" : "=r"(a) : "l"(p));
    return a;
}
__device__ __forceinline__ float to_tf32(float x) {
    uint32_t u; asm("cvt.rna.tf32.f32 %0, %1;" : "=r"(u) : "f"(x));
    return __uint_as_float(u);
}
__device__ __forceinline__ void cpa16(uint32_t dst, const float* src) {
    asm volatile("cp.async.cg.shared.global [%0], [%1], 16;" :: "r"(dst), "l"(src) : "memory");
}
__device__ __forceinline__ void mma_tf32(float* d, const uint32_t* a, const uint32_t* b) {
    asm volatile(
        "mma.sync.aligned.m16n8k8.row.col.f32.tf32.tf32.f32 "
        "{%0,%1,%2,%3}, {%4,%5,%6,%7}, {%8,%9}, {%0,%1,%2,%3};\n"
        : "+f"(d[0]), "+f"(d[1]), "+f"(d[2]), "+f"(d[3])
        : "r"(a[0]), "r"(a[1]), "r"(a[2]), "r"(a[3]), "r"(b[0]), "r"(b[1]));
}

// ---------------- weight prep kernels ----------------

__global__ void k_prep_w1(const float* __restrict__ cw, const float* __restrict__ cb,
                          const float* __restrict__ gam, const float* __restrict__ bet,
                          const float* __restrict__ mean, const float* __restrict__ var) {
    int i = blockIdx.x * blockDim.x + threadIdx.x;
    if (i >= FEAT * 64) return;
    int f = i / 64, c = i % 64;
    float s = gam[c] * rsqrtf(var[c] + 1e-5f);
    g_W1[f * 64 + c] = cw[c * (FEAT * 3) + f * 3 + 1] * s;
    if (f == 0) g_b1[c] = (cb[c] - mean[c]) * s + bet[c];
}

__global__ void k_S(const float* __restrict__ lin_w) {
    int idx = blockIdx.x * blockDim.x + threadIdx.x;
    if (idx >= 1024 * 64) return;
    int o = idx >> 6, c = idx & 63;
    float s = 0.f;
#pragma unroll
    for (int j = 0; j < 16; j++) s += lin_w[(size_t)o * 1024 + (c << 4) + j];
    g_S[idx] = s;
}

__global__ void k_buildQ(const float* __restrict__ cell_w, const float* __restrict__ cell_b,
                         const float* __restrict__ lin_b) {
    int idx = blockIdx.x * blockDim.x + threadIdx.x;
    if (idx >= 4096 * 64) return;
    int j = idx / 64, c = idx % 64;
    int gate = j / 2048;               // 0 = i, 1 = f(x part)
    int jj = j % 2048;
    int co = jj / 16, p = jj % 16;
    int py = p / 4, px = p % 4;
    int wco = (gate == 0) ? co : 128 + co;
    int nci = (gate == 0) ? 48 : 16;
    float acc = 0.f, bacc = 0.f;
    for (int ci = 0; ci < nci; ci++) {
        int xch = (gate == 0) ? ci : 48 + ci;
        for (int ky = 0; ky < 3; ky++) {
            int qy = py + ky - 1; if (qy < 0 || qy > 3) continue;
            for (int kx = 0; kx < 3; kx++) {
                int qx = px + kx - 1; if (qx < 0 || qx > 3) continue;
                float w = cell_w[(size_t)wco * 432 + ci * 9 + ky * 3 + kx];
                int o = xch * 16 + qy * 4 + qx;
                acc += w * g_S[o * 64 + c];
                if (c == 0) bacc += w * lin_b[o];
            }
        }
    }
    g_QT[(size_t)j * 64 + c] = to_tf32(acc);               // transposed [j][k], tf32-rounded
    if (c == 0) g_bias_if[j] = cell_b[wco] + bacc;
}

__global__ void k_buildWh(const float* __restrict__ cell_w, const float* __restrict__ cell_b) {
    size_t idx = (size_t)blockIdx.x * blockDim.x + threadIdx.x;
    if (idx >= (size_t)2048 * 2048) return;
    int j = (int)(idx % 2048);
    int r = (int)(idx / 2048);
    int co = j / 16, p = j % 16, py = p / 4, px = p % 4;
    float* dst; int wco, lin;
    if (r < 512)        { dst = &g_WfT[(size_t)j * 512 + r];          wco = 128 + co; lin = 16 + r / 16; }
    else if (r < 1280)  { int rr = r - 512;  dst = &g_WoT[(size_t)j * 768 + rr]; wco = 256 + co; lin = rr / 16; }
    else                { int rr = r - 1280; dst = &g_WgT[(size_t)j * 768 + rr]; wco = 384 + co; lin = rr / 16; }
    int q = r % 16, qy = q / 4, qx = q % 4;
    int ky = qy - py + 1, kx = qx - px + 1;
    float v = 0.f;
    if (ky >= 0 && ky < 3 && kx >= 0 && kx < 3)
        v = cell_w[(size_t)wco * 432 + lin * 9 + ky * 3 + kx];
    *dst = to_tf32(v);
    if (r == 0) g_bias_o[j] = cell_b[256 + co];
    if (r == 1) g_bias_g[j] = cell_b[384 + co];
}

// ---------------- encoder ----------------

__global__ void k_enc(const float* __restrict__ x) {
    __shared__ float sW[FEAT * 64];
    __shared__ float sb[64];
    __shared__ float sx[32][FEAT];
    int tid = threadIdx.x;
    for (int i = tid; i < FEAT * 64; i += 256) sW[i] = g_W1[i];
    if (tid < 64) sb[tid] = g_b1[tid];
    size_t row0 = (size_t)blockIdx.x * 32;
    for (int i = tid; i < 32 * FEAT; i += 256) {
        int r = i / FEAT, f = i % FEAT;
        sx[r][f] = x[(row0 + r) * FEAT + f];
    }
    __syncthreads();
    int c = tid & 63;
    int rg = tid >> 6;
    for (int rr = 0; rr < 8; rr++) {
        int r = rg * 8 + rr;
        float acc = sb[c];
#pragma unroll 4
        for (int f = 0; f < FEAT; f++) acc += sx[r][f] * sW[f * 64 + c];
        g_enc[(row0 + r) * 64 + c] = to_tf32(fmaxf(acc, 0.f));
    }
}

__global__ void k_zero() {
    size_t i = (size_t)blockIdx.x * blockDim.x + threadIdx.x;
    if (i < (size_t)BATCH * 2048) { g_h[0][i] = 0.f; g_c[i] = 0.f; }
}

// ---------------- tf32 mma.sync recurrent step ----------------
// SMEM per stage: sA[64][36] | sB[64][36] | sB2[64][36]  (36 = 32 + pad4)
#define TILE_F (64 * 36)                 // floats per tile
#define STAGE_B (3 * TILE_F * 4)         // 27648 bytes
#define STEP_SMEM (2 * STAGE_B)          // 55296 bytes
#define NCHUNK 66                        // 2(enc: i+f) + 16(f) + 24(o) + 24(g)

__global__ void __launch_bounds__(128) k_step(int t) {
    extern __shared__ __align__(128) char smem[];
    const int tid = threadIdx.x;
    const int wid = tid >> 5;
    const int lane = tid & 31;
    const int gid = lane >> 2;           // group-of-4 id (0..7)
    const int tig = lane & 3;            // thread-in-group
    const int warp_m = wid >> 1;         // 0..1  -> m offset warp_m*32
    const int warp_n = wid & 1;          // 0..1  -> n offset warp_n*32
    const int bb = blockIdx.x << 6;
    const int jj = blockIdx.y << 6;
    const float* __restrict__ hin = g_h[t & 1];
    float* __restrict__ hout = g_h[(t & 1) ^ 1];
    const float* enc_t = g_enc + ((size_t)bb * TSTEPS + t) * 64;
    const float* hrow = hin + (size_t)bb * 2048;
    const uint32_t sbase = smem_u32(smem);

    float acc_i[32], acc_f[32], acc_o[32], acc_g[32];
#pragma unroll
    for (int e = 0; e < 32; e++) { acc_i[e] = 0.f; acc_f[e] = 0.f; acc_o[e] = 0.f; acc_g[e] = 0.f; }

    const int prow = tid >> 1;           // 0..63
    const int phalf = tid & 1;           // 0..1 (16 floats each)

    auto produce = [&](int chunk) {
        int s = chunk & 1;
        const float *Ap, *Bp, *B2p = nullptr;
        size_t Astr, Bstr;
        if (chunk < 2) {
            int ch = chunk;
            Ap = enc_t + ch * 32; Astr = (size_t)TSTEPS * 64;
            Bp = g_QT + (size_t)jj * 64 + ch * 32; Bstr = 64;
            B2p = g_QT + (size_t)(2048 + jj) * 64 + ch * 32;
        } else if (chunk < 18) {
            int ch = chunk - 2;
            Ap = hrow + ch * 32; Astr = 2048;
            Bp = g_WfT + (size_t)jj * 512 + ch * 32; Bstr = 512;
        } else if (chunk < 42) {
            int ch = chunk - 18;
            Ap = hrow + 512 + ch * 32; Astr = 2048;
            Bp = g_WoT + (size_t)jj * 768 + ch * 32; Bstr = 768;
        } else {
            int ch = chunk - 42;
            Ap = hrow + 1280 + ch * 32; Astr = 2048;
            Bp = g_WgT + (size_t)jj * 768 + ch * 32; Bstr = 768;
        }
        uint32_t dA = sbase + s * STAGE_B + prow * 144 + phalf * 64;
        const float* sa = Ap + (size_t)prow * Astr + phalf * 16;
#pragma unroll
        for (int q = 0; q < 4; q++) cpa16(dA + q * 16, sa + q * 4);
        uint32_t dB = dA + TILE_F * 4;
        const float* sbp = Bp + (size_t)prow * Bstr + phalf * 16;
#pragma unroll
        for (int q = 0; q < 4; q++) cpa16(dB + q * 16, sbp + q * 4);
        if (B2p) {
            uint32_t dB2 = dB + TILE_F * 4;
            const float* sb2 = B2p + (size_t)prow * 64 + phalf * 16;
#pragma unroll
            for (int q = 0; q < 4; q++) cpa16(dB2 + q * 16, sb2 + q * 4);
        }
        asm volatile("cp.async.commit_group;" ::: "memory");
    };

    auto compute = [&](int chunk) {
        int s = chunk & 1;
        const float* sA = (const float*)(smem + (size_t)s * STAGE_B);
        const float* sB = sA + TILE_F;
        const float* sB2 = sB + TILE_F;
        float* accA;
        bool dual = false;
        if (chunk < 2)       { accA = acc_i; dual = true; }
        else if (chunk < 18) { accA = acc_f; }
        else if (chunk < 42) { accA = acc_o; }
        else                 { accA = acc_g; }
#pragma unroll
        for (int ks = 0; ks < 4; ks++) {
            int k0 = ks * 8;
            uint32_t a[2][4];
#pragma unroll
            for (int mt = 0; mt < 2; mt++) {
                int r0 = warp_m * 32 + mt * 16 + gid;
                a[mt][0] = __float_as_uint(sA[r0 * 36 + k0 + tig]);
                a[mt][1] = __float_as_uint(sA[(r0 + 8) * 36 + k0 + tig]);
                a[mt][2] = __float_as_uint(sA[r0 * 36 + k0 + tig + 4]);
                a[mt][3] = __float_as_uint(sA[(r0 + 8) * 36 + k0 + tig + 4]);
            }
            uint32_t b[4][2];
#pragma unroll
            for (int nt = 0; nt < 4; nt++) {
                int c0 = warp_n * 32 + nt * 8 + gid;
                b[nt][0] = __float_as_uint(sB[c0 * 36 + k0 + tig]);
                b[nt][1] = __float_as_uint(sB[c0 * 36 + k0 + tig + 4]);
            }
#pragma unroll
            for (int mt = 0; mt < 2; mt++)
#pragma unroll
                for (int nt = 0; nt < 4; nt++)
                    mma_tf32(accA + (mt * 4 + nt) * 4, a[mt], b[nt]);
            if (dual) {
                uint32_t b2[4][2];
#pragma unroll
                for (int nt = 0; nt < 4; nt++) {
                    int c0 = warp_n * 32 + nt * 8 + gid;
                    b2[nt][0] = __float_as_uint(sB2[c0 * 36 + k0 + tig]);
                    b2[nt][1] = __float_as_uint(sB2[c0 * 36 + k0 + tig + 4]);
                }
#pragma unroll
                for (int mt = 0; mt < 2; mt++)
#pragma unroll
                    for (int nt = 0; nt < 4; nt++)
                        mma_tf32(acc_f + (mt * 4 + nt) * 4, a[mt], b2[nt]);
            }
        }
    };

    produce(0);
#pragma unroll 1
    for (int i = 0; i < NCHUNK; i++) {
        if (i + 1 < NCHUNK) {
            produce(i + 1);
            asm volatile("cp.async.wait_group 1;" ::: "memory");
        } else {
            asm volatile("cp.async.wait_group 0;" ::: "memory");
        }
        __syncthreads();
        compute(i);
        __syncthreads();
    }

    // ---- fused LSTM epilogue ----
#pragma unroll
    for (int mt = 0; mt < 2; mt++) {
#pragma unroll
        for (int nt = 0; nt < 4; nt++) {
            int fi = (mt * 4 + nt) * 4;
            int colbase = jj + warp_n * 32 + nt * 8 + tig * 2;
#pragma unroll
            for (int h2 = 0; h2 < 2; h2++) {
                int b = bb + warp_m * 32 + mt * 16 + gid + h2 * 8;
                size_t off = (size_t)b * 2048 + colbase;
                float2 cold = *(const float2*)(g_c + off);
                float cold2[2] = {cold.x, cold.y};
                float cn[2], hn[2];
#pragma unroll
                for (int e2 = 0; e2 < 2; e2++) {
                    int e = fi + h2 * 2 + e2;
                    int j = colbase + e2;
                    float pi = acc_i[e] + g_bias_if[j];
                    float pf = acc_f[e] + g_bias_if[2048 + j];
                    float po = acc_o[e] + g_bias_o[j];
                    float pg = acc_g[e] + g_bias_g[j];
                    float si = 1.f / (1.f + __expf(-pi));
                    float sf = 1.f / (1.f + __expf(-pf));
                    float so = 1.f / (1.f + __expf(-po));
                    float tg = 2.f / (1.f + __expf(-2.f * pg)) - 1.f;
                    float c2 = sf * cold2[e2] + si * tg;
                    cn[e2] = c2;
                    float tc = 2.f / (1.f + __expf(-2.f * c2)) - 1.f;
                    hn[e2] = to_tf32(so * tc);
                }
                *(float2*)(g_c + off)  = make_float2(cn[0], cn[1]);
                *(float2*)(hout + off) = make_float2(hn[0], hn[1]);
            }
        }
    }
}

// ---------------- classifier ----------------

__global__ void k_cls1(const float* __restrict__ w, const float* __restrict__ bias) {
    __shared__ float sf[16][64];
    __shared__ float sw[64][129];
    const float* hptr = g_h[0];
    int tid = threadIdx.x;
    int b0 = blockIdx.x * 16;
    float acc[16];
#pragma unroll
    for (int r = 0; r < 16; r++) acc[r] = 0.f;
    for (int k0 = 0; k0 < 2048; k0 += 64) {
        __syncthreads();
        for (int i = tid; i < 16 * 64; i += 128) {
            int r = i / 64, kl = i % 64;
            sf[r][kl] = hptr[(size_t)(b0 + r) * 2048 + k0 + kl];
        }
        {
            int kl = tid % 64, og = tid / 64;
            for (int o = og; o < 128; o += 2)
                sw[kl][o] = w[(size_t)o * 2048 + k0 + kl];
        }
        __syncthreads();
        for (int kl = 0; kl < 64; kl++) {
            float wv = sw[kl][tid];
#pragma unroll
            for (int r = 0; r < 16; r++) acc[r] += sf[r][kl] * wv;
        }
    }
    for (int r = 0; r < 16; r++)
        g_hid[(size_t)(b0 + r) * 128 + tid] = fmaxf(acc[r] + bias[tid], 0.f);
}

__global__ void k_cls2(const float* __restrict__ w, const float* __restrict__ b,
                       float* __restrict__ out) {
    int bi = blockIdx.x * blockDim.x + threadIdx.x;
    if (bi >= BATCH) return;
    float a0 = b[0], a1 = b[1];
    for (int k = 0; k < 128; k++) {
        float h = g_hid[(size_t)bi * 128 + k];
        a0 += h * w[k];
        a1 += h * w[128 + k];
    }
    out[bi * 2 + 0] = a0;
    out[bi * 2 + 1] = a1;
}

// ---------------- launch ----------------

extern "C" void kernel_launch(void* const* d_in, const int* in_sizes, int n_in,
                              void* d_out, int out_size) {
    const float* x        = (const float*)d_in[0];
    const float* conv1d_w = (const float*)d_in[1];
    const float* conv1d_b = (const float*)d_in[2];
    const float* bn_gamma = (const float*)d_in[3];
    const float* bn_beta  = (const float*)d_in[4];
    const float* bn_mean  = (const float*)d_in[5];
    const float* bn_var   = (const float*)d_in[6];
    const float* lin_w    = (const float*)d_in[7];
    const float* lin_b    = (const float*)d_in[8];
    const float* cell_w   = (const float*)d_in[9];
    const float* cell_b   = (const float*)d_in[10];
    const float* cls1_w   = (const float*)d_in[11];
    const float* cls1_b   = (const float*)d_in[12];
    const float* cls2_w   = (const float*)d_in[13];
    const float* cls2_b   = (const float*)d_in[14];
    float* out = (float*)d_out;

    cudaFuncSetAttribute(k_step, cudaFuncAttributeMaxDynamicSharedMemorySize, STEP_SMEM);

    k_prep_w1<<<(FEAT * 64 + 255) / 256, 256>>>(conv1d_w, conv1d_b, bn_gamma, bn_beta, bn_mean, bn_var);
    k_S<<<(1024 * 64 + 255) / 256, 256>>>(lin_w);
    k_buildQ<<<(4096 * 64 + 255) / 256, 256>>>(cell_w, cell_b, lin_b);
    k_buildWh<<<(int)(((size_t)2048 * 2048 + 255) / 256), 256>>>(cell_w, cell_b);
    k_enc<<<BT / 32, 256>>>(x);
    k_zero<<<(int)(((size_t)BATCH * 2048 + 255) / 256), 256>>>();

    for (int t = 0; t < TSTEPS; t++)
        k_step<<<dim3(BATCH / 64, 2048 / 64), 128, STEP_SMEM>>>(t);

    k_cls1<<<BATCH / 16, 128>>>(cls1_w, cls1_b);
    k_cls2<<<(BATCH + 127) / 128, 128>>>(cls2_w, cls2_b, out);
}

// round 10
// speedup vs baseline: 1.7475x; 1.7475x over previous
#include <cuda_runtime.h>
#include <math.h>
#include <cstdint>

// ---------------------------------------------------------------------------
// FastConvLSTM restructured, fp32 recurrence on packed FFMA2 (fma.rn.f32x2):
//   enc  = relu((x @ W1c)*bn_s + b1)                 [B*T, 64]
//   pre_i = enc @ Qi ;  pre_f = enc @ Qf + h[0:512] @ Wf
//   pre_o = h[512:1280] @ Wo ;  pre_g = h[1280:2048] @ Wg
//   c = sig(pre_f)*c + sig(pre_i)*tanh(pre_g); h = sig(pre_o)*tanh(c)
// Step kernel: CTA 64x64 tile, 256 threads, thread tile 4x4 per gate,
// accumulators packed as f32x2 row-pairs, B duplicated per-lane via mov.b64.
// ---------------------------------------------------------------------------

#define BATCH 2048
#define TSTEPS 128
#define FEAT 84
#define BT (BATCH * TSTEPS)

typedef unsigned long long ull;

__device__ __align__(128) float g_W1[FEAT * 64];
__device__ __align__(128) float g_b1[64];
__device__ __align__(128) float g_S[1024 * 64];        // S[o][c]
__device__ __align__(128) float g_Q[64 * 4096];        // [k][j]; j: [0,2048)=i, [2048,4096)=f
__device__ __align__(128) float g_bias_if[4096];
__device__ __align__(128) float g_Wf[512 * 2048];      // [k][j]
__device__ __align__(128) float g_Wo[768 * 2048];
__device__ __align__(128) float g_Wg[768 * 2048];
__device__ __align__(128) float g_bias_o[2048];
__device__ __align__(128) float g_bias_g[2048];
__device__ __align__(128) float g_enc[(size_t)BT * 64];
__device__ __align__(128) float g_h[2][(size_t)BATCH * 2048];
__device__ __align__(128) float g_c[(size_t)BATCH * 2048];
__device__ __align__(128) float g_hid[(size_t)BATCH * 128];

// ---------------- f32x2 helpers ----------------

__device__ __forceinline__ uint32_t smem_u32(const void* p) {
    uint32_t a;
    asm("{ .reg .u64 t; cvta.to.shared.u64 t, %1; cvt.u32.u64 %0, t; }" : "=r"(a) : "l"(p));
    return a;
}
__device__ __forceinline__ void lds_a2(ull& x, ull& y, uint32_t addr) {
    asm volatile("ld.shared.v2.u64 {%0,%1}, [%2];" : "=l"(x), "=l"(y) : "r"(addr));
}
__device__ __forceinline__ void lds_b4(uint32_t& x, uint32_t& y, uint32_t& z, uint32_t& w, uint32_t addr) {
    asm volatile("ld.shared.v4.b32 {%0,%1,%2,%3}, [%4];" : "=r"(x), "=r"(y), "=r"(z), "=r"(w) : "r"(addr));
}
__device__ __forceinline__ ull dup2(uint32_t b) {
    ull d; asm("mov.b64 %0, {%1,%1};" : "=l"(d) : "r"(b)); return d;
}
__device__ __forceinline__ void fma2(ull& d, ull a, ull b) {
    asm("fma.rn.f32x2 %0, %1, %2, %0;" : "+l"(d) : "l"(a), "l"(b));
}
__device__ __forceinline__ float xlo(ull v) { return __uint_as_float((uint32_t)v); }
__device__ __forceinline__ float xhi(ull v) { return __uint_as_float((uint32_t)(v >> 32)); }

// ---------------- weight prep kernels (cheap, run every launch) ----------------

__global__ void k_prep_w1(const float* __restrict__ cw, const float* __restrict__ cb,
                          const float* __restrict__ gam, const float* __restrict__ bet,
                          const float* __restrict__ mean, const float* __restrict__ var) {
    int i = blockIdx.x * blockDim.x + threadIdx.x;
    if (i >= FEAT * 64) return;
    int f = i / 64, c = i % 64;
    float s = gam[c] * rsqrtf(var[c] + 1e-5f);
    g_W1[f * 64 + c] = cw[c * (FEAT * 3) + f * 3 + 1] * s;   // center tap only
    if (f == 0) g_b1[c] = (cb[c] - mean[c]) * s + bet[c];
}

__global__ void k_S(const float* __restrict__ lin_w) {
    int idx = blockIdx.x * blockDim.x + threadIdx.x;
    if (idx >= 1024 * 64) return;
    int o = idx >> 6, c = idx & 63;
    float s = 0.f;
#pragma unroll
    for (int j = 0; j < 16; j++) s += lin_w[(size_t)o * 1024 + (c << 4) + j];
    g_S[idx] = s;
}

__global__ void k_buildQ(const float* __restrict__ cell_w, const float* __restrict__ cell_b,
                         const float* __restrict__ lin_b) {
    int idx = blockIdx.x * blockDim.x + threadIdx.x;
    if (idx >= 4096 * 64) return;
    int j = idx / 64, c = idx % 64;
    int gate = j / 2048;               // 0 = i, 1 = f(x part)
    int jj = j % 2048;
    int co = jj / 16, p = jj % 16;
    int py = p / 4, px = p % 4;
    int wco = (gate == 0) ? co : 128 + co;
    int nci = (gate == 0) ? 48 : 16;
    float acc = 0.f, bacc = 0.f;
    for (int ci = 0; ci < nci; ci++) {
        int xch = (gate == 0) ? ci : 48 + ci;
        for (int ky = 0; ky < 3; ky++) {
            int qy = py + ky - 1; if (qy < 0 || qy > 3) continue;
            for (int kx = 0; kx < 3; kx++) {
                int qx = px + kx - 1; if (qx < 0 || qx > 3) continue;
                float w = cell_w[(size_t)wco * 432 + ci * 9 + ky * 3 + kx];
                int o = xch * 16 + qy * 4 + qx;
                acc += w * g_S[o * 64 + c];
                if (c == 0) bacc += w * lin_b[o];
            }
        }
    }
    g_Q[(size_t)c * 4096 + j] = acc;
    if (c == 0) g_bias_if[j] = cell_b[wco] + bacc;
}

__global__ void k_buildWh(const float* __restrict__ cell_w, const float* __restrict__ cell_b) {
    size_t idx = (size_t)blockIdx.x * blockDim.x + threadIdx.x;
    if (idx >= (size_t)2048 * 2048) return;
    int j = (int)(idx % 2048);
    int r = (int)(idx / 2048);         // rows across f(512) | o(768) | g(768)
    int co = j / 16, p = j % 16, py = p / 4, px = p % 4;
    float* dst; int wco, lin;
    if (r < 512)        { dst = &g_Wf[(size_t)r * 2048 + j];          wco = 128 + co; lin = 16 + r / 16; }
    else if (r < 1280)  { int rr = r - 512;  dst = &g_Wo[(size_t)rr * 2048 + j]; wco = 256 + co; lin = rr / 16; }
    else                { int rr = r - 1280; dst = &g_Wg[(size_t)rr * 2048 + j]; wco = 384 + co; lin = rr / 16; }
    int q = r % 16, qy = q / 4, qx = q % 4;
    int ky = qy - py + 1, kx = qx - px + 1;
    float v = 0.f;
    if (ky >= 0 && ky < 3 && kx >= 0 && kx < 3)
        v = cell_w[(size_t)wco * 432 + lin * 9 + ky * 3 + kx];
    *dst = v;
    if (r == 0) g_bias_o[j] = cell_b[256 + co];
    if (r == 1) g_bias_g[j] = cell_b[384 + co];
}

// ---------------- encoder ----------------

__global__ void k_enc(const float* __restrict__ x) {
    __shared__ float sW[FEAT * 64];
    __shared__ float sb[64];
    __shared__ float sx[32][FEAT];
    int tid = threadIdx.x;
    for (int i = tid; i < FEAT * 64; i += 256) sW[i] = g_W1[i];
    if (tid < 64) sb[tid] = g_b1[tid];
    size_t row0 = (size_t)blockIdx.x * 32;
    for (int i = tid; i < 32 * FEAT; i += 256) {
        int r = i / FEAT, f = i % FEAT;
        sx[r][f] = x[(row0 + r) * FEAT + f];
    }
    __syncthreads();
    int c = tid & 63;
    int rg = tid >> 6;
    for (int rr = 0; rr < 8; rr++) {
        int r = rg * 8 + rr;
        float acc = sb[c];
#pragma unroll 4
        for (int f = 0; f < FEAT; f++) acc += sx[r][f] * sW[f * 64 + c];
        g_enc[(row0 + r) * 64 + c] = fmaxf(acc, 0.f);
    }
}

__global__ void k_zero() {
    size_t i = (size_t)blockIdx.x * blockDim.x + threadIdx.x;
    if (i < (size_t)BATCH * 2048) { g_h[0][i] = 0.f; g_c[i] = 0.f; }
}

// ---------------- recurrent step: FFMA2 GEMM phases + fused LSTM ----------------

template <int NKT, bool DUAL>
__device__ __forceinline__ void gphase(
    ull (&acc)[8], ull* acc2,
    const float* __restrict__ uB, size_t uStr,
    const float* __restrict__ wB, const float* __restrict__ w2B, int wld,
    float (*us)[64], float (*ws)[64], float (*ws2)[64],
    uint32_t us_b, uint32_t ws_b, uint32_t ws2_b,
    int tid, int tx, int ty)
{
    const int lb = tid >> 2, lk4 = (tid & 3) << 2;
    const int wk = tid >> 4, wj4 = (tid & 15) << 2;
    const float* up = uB + (size_t)lb * uStr + lk4;
    const float* wp = wB + (size_t)wk * wld + wj4;
    const float* w2p = DUAL ? (w2B + (size_t)wk * wld + wj4) : wB;
    float4 uv = *(const float4*)up;
    float4 wv = *(const float4*)wp;
    float4 w2v;
    if (DUAL) w2v = *(const float4*)w2p;
    const uint32_t aaddr = us_b + (uint32_t)(ty * 4) * 4;
    const uint32_t baddr = ws_b + (uint32_t)(tx * 4) * 4;
    const uint32_t b2addr = ws2_b + (uint32_t)(tx * 4) * 4;

#pragma unroll 1
    for (int kt = 0; kt < NKT; kt++) {
        __syncthreads();
        us[lk4 + 0][lb] = uv.x; us[lk4 + 1][lb] = uv.y;
        us[lk4 + 2][lb] = uv.z; us[lk4 + 3][lb] = uv.w;
        *(float4*)&ws[wk][wj4] = wv;
        if (DUAL) *(float4*)&ws2[wk][wj4] = w2v;
        __syncthreads();
        if (kt + 1 < NKT) {
            uv = *(const float4*)(up + (size_t)(kt + 1) * 16);
            wv = *(const float4*)(wp + (size_t)(kt + 1) * 16 * wld);
            if (DUAL) w2v = *(const float4*)(w2p + (size_t)(kt + 1) * 16 * wld);
        }
#pragma unroll
        for (int k = 0; k < 16; k++) {
            ull a01, a23;
            lds_a2(a01, a23, aaddr + k * 256);
            uint32_t b0, b1, b2, b3;
            lds_b4(b0, b1, b2, b3, baddr + k * 256);
            ull B0 = dup2(b0), B1 = dup2(b1), B2 = dup2(b2), B3 = dup2(b3);
            fma2(acc[0], a01, B0); fma2(acc[1], a01, B1);
            fma2(acc[2], a01, B2); fma2(acc[3], a01, B3);
            fma2(acc[4], a23, B0); fma2(acc[5], a23, B1);
            fma2(acc[6], a23, B2); fma2(acc[7], a23, B3);
            if (DUAL) {
                uint32_t c0, c1, c2, c3;
                lds_b4(c0, c1, c2, c3, b2addr + k * 256);
                ull C0 = dup2(c0), C1 = dup2(c1), C2 = dup2(c2), C3 = dup2(c3);
                fma2(acc2[0], a01, C0); fma2(acc2[1], a01, C1);
                fma2(acc2[2], a01, C2); fma2(acc2[3], a01, C3);
                fma2(acc2[4], a23, C0); fma2(acc2[5], a23, C1);
                fma2(acc2[6], a23, C2); fma2(acc2[7], a23, C3);
            }
        }
    }
}

__global__ void __launch_bounds__(256, 2) k_step(int t) {
    __shared__ float us[16][64];
    __shared__ float ws[16][64];
    __shared__ float ws2[16][64];
    const int tid = threadIdx.x;
    const int tx = tid & 15, ty = tid >> 4;
    const int bb = blockIdx.x << 6;
    const int jj = blockIdx.y << 6;
    const float* __restrict__ hin = g_h[t & 1];
    float* __restrict__ hout = g_h[(t & 1) ^ 1];
    const float* enc_t = g_enc + ((size_t)bb * TSTEPS + t) * 64;
    const float* hrow = hin + (size_t)bb * 2048;
    const uint32_t us_b = smem_u32(us), ws_b = smem_u32(ws), ws2_b = smem_u32(ws2);

    ull acc_i[8], acc_f[8], acc_o[8], acc_g[8];
#pragma unroll
    for (int e = 0; e < 8; e++) { acc_i[e] = 0ull; acc_f[e] = 0ull; acc_o[e] = 0ull; acc_g[e] = 0ull; }

    // Phase A: enc (K=64) -> gates i and f(x-part), shared A tile
    gphase<4, true>(acc_i, acc_f, enc_t, (size_t)TSTEPS * 64,
                    g_Q + jj, g_Q + 2048 + jj, 4096,
                    us, ws, ws2, us_b, ws_b, ws2_b, tid, tx, ty);
    // Phase B: h[0:512] -> gate f
    gphase<32, false>(acc_f, nullptr, hrow, 2048, g_Wf + jj, nullptr, 2048,
                      us, ws, ws2, us_b, ws_b, ws2_b, tid, tx, ty);
    // Phase C: h[512:1280] -> gate o
    gphase<48, false>(acc_o, nullptr, hrow + 512, 2048, g_Wo + jj, nullptr, 2048,
                      us, ws, ws2, us_b, ws_b, ws2_b, tid, tx, ty);
    // Phase D: h[1280:2048] -> gate g
    gphase<48, false>(acc_g, nullptr, hrow + 1280, 2048, g_Wg + jj, nullptr, 2048,
                      us, ws, ws2, us_b, ws_b, ws2_b, tid, tx, ty);

    // ---- fused LSTM epilogue (no gate traffic to DRAM) ----
    const int rbase = bb + (ty << 2);
    const int cbase = jj + (tx << 2);
#pragma unroll
    for (int rp = 0; rp < 2; rp++) {
#pragma unroll
        for (int hl = 0; hl < 2; hl++) {
            int b = rbase + rp * 2 + hl;
            size_t off = (size_t)b * 2048 + cbase;
            float4 cold = *(const float4*)(g_c + off);
            float cold4[4] = {cold.x, cold.y, cold.z, cold.w};
            float cn[4], hn[4];
#pragma unroll
            for (int c = 0; c < 4; c++) {
                int e = rp * 4 + c;
                int j = cbase + c;
                float pi = (hl ? xhi(acc_i[e]) : xlo(acc_i[e])) + g_bias_if[j];
                float pf = (hl ? xhi(acc_f[e]) : xlo(acc_f[e])) + g_bias_if[2048 + j];
                float po = (hl ? xhi(acc_o[e]) : xlo(acc_o[e])) + g_bias_o[j];
                float pg = (hl ? xhi(acc_g[e]) : xlo(acc_g[e])) + g_bias_g[j];
                float si = 1.f / (1.f + __expf(-pi));
                float sf = 1.f / (1.f + __expf(-pf));
                float so = 1.f / (1.f + __expf(-po));
                float tg = 2.f / (1.f + __expf(-2.f * pg)) - 1.f;
                float c2 = sf * cold4[c] + si * tg;
                cn[c] = c2;
                float tc = 2.f / (1.f + __expf(-2.f * c2)) - 1.f;
                hn[c] = so * tc;
            }
            *(float4*)(g_c + off)  = make_float4(cn[0], cn[1], cn[2], cn[3]);
            *(float4*)(hout + off) = make_float4(hn[0], hn[1], hn[2], hn[3]);
        }
    }
}

// ---------------- classifier ----------------

__global__ void k_cls1(const float* __restrict__ w, const float* __restrict__ bias) {
    __shared__ float sf[16][64];
    __shared__ float sw[64][129];
    const float* hptr = g_h[0];
    int tid = threadIdx.x;
    int b0 = blockIdx.x * 16;
    float acc[16];
#pragma unroll
    for (int r = 0; r < 16; r++) acc[r] = 0.f;
    for (int k0 = 0; k0 < 2048; k0 += 64) {
        __syncthreads();
        for (int i = tid; i < 16 * 64; i += 128) {
            int r = i / 64, kl = i % 64;
            sf[r][kl] = hptr[(size_t)(b0 + r) * 2048 + k0 + kl];
        }
        {
            int kl = tid % 64, og = tid / 64;
            for (int o = og; o < 128; o += 2)
                sw[kl][o] = w[(size_t)o * 2048 + k0 + kl];
        }
        __syncthreads();
        for (int kl = 0; kl < 64; kl++) {
            float wv = sw[kl][tid];
#pragma unroll
            for (int r = 0; r < 16; r++) acc[r] += sf[r][kl] * wv;
        }
    }
    for (int r = 0; r < 16; r++)
        g_hid[(size_t)(b0 + r) * 128 + tid] = fmaxf(acc[r] + bias[tid], 0.f);
}

__global__ void k_cls2(const float* __restrict__ w, const float* __restrict__ b,
                       float* __restrict__ out) {
    int bi = blockIdx.x * blockDim.x + threadIdx.x;
    if (bi >= BATCH) return;
    float a0 = b[0], a1 = b[1];
    for (int k = 0; k < 128; k++) {
        float h = g_hid[(size_t)bi * 128 + k];
        a0 += h * w[k];
        a1 += h * w[128 + k];
    }
    out[bi * 2 + 0] = a0;
    out[bi * 2 + 1] = a1;
}

// ---------------- launch ----------------

extern "C" void kernel_launch(void* const* d_in, const int* in_sizes, int n_in,
                              void* d_out, int out_size) {
    const float* x        = (const float*)d_in[0];
    const float* conv1d_w = (const float*)d_in[1];
    const float* conv1d_b = (const float*)d_in[2];
    const float* bn_gamma = (const float*)d_in[3];
    const float* bn_beta  = (const float*)d_in[4];
    const float* bn_mean  = (const float*)d_in[5];
    const float* bn_var   = (const float*)d_in[6];
    const float* lin_w    = (const float*)d_in[7];
    const float* lin_b    = (const float*)d_in[8];
    const float* cell_w   = (const float*)d_in[9];
    const float* cell_b   = (const float*)d_in[10];
    const float* cls1_w   = (const float*)d_in[11];
    const float* cls1_b   = (const float*)d_in[12];
    const float* cls2_w   = (const float*)d_in[13];
    const float* cls2_b   = (const float*)d_in[14];
    float* out = (float*)d_out;

    k_prep_w1<<<(FEAT * 64 + 255) / 256, 256>>>(conv1d_w, conv1d_b, bn_gamma, bn_beta, bn_mean, bn_var);
    k_S<<<(1024 * 64 + 255) / 256, 256>>>(lin_w);
    k_buildQ<<<(4096 * 64 + 255) / 256, 256>>>(cell_w, cell_b, lin_b);
    k_buildWh<<<(int)(((size_t)2048 * 2048 + 255) / 256), 256>>>(cell_w, cell_b);
    k_enc<<<BT / 32, 256>>>(x);
    k_zero<<<(int)(((size_t)BATCH * 2048 + 255) / 256), 256>>>();

    for (int t = 0; t < TSTEPS; t++)
        k_step<<<dim3(BATCH / 64, 2048 / 64), 256>>>(t);

    k_cls1<<<BATCH / 16, 128>>>(cls1_w, cls1_b);
    k_cls2<<<(BATCH + 127) / 128, 128>>>(cls2_w, cls2_b, out);
}

// round 11
// speedup vs baseline: 3.3299x; 1.9055x over previous
#include <cuda_runtime.h>
#include <math.h>
#include <cstdint>

// ---------------------------------------------------------------------------
// FastConvLSTM, position-major block-sparse recurrence + FFMA2:
//   h/c layout: [b][pos*128 + ch]  (pos = y*4+x, 16 positions, 128 channels)
//   pre_f(p) = enc @ Qf(p) + sum_{q in N(p)} h[q, 0:32]   @ Wblk[d][0:32]
//   pre_o(p) =               sum_{q in N(p)} h[q, 32:80]  @ Wblk[d][32:80]
//   pre_g(p) =               sum_{q in N(p)} h[q, 80:128] @ Wblk[d][80:128]
//   pre_i(p) = enc @ Qi(p)
//   c = sig(pre_f)*c + sig(pre_i)*tanh(pre_g); h = sig(pre_o)*tanh(c)
// Step CTA: one (64-batch, position p) tile, N=128 channels, 256 threads,
// thread tile 4x8, j-paired f32x2 accumulators (fma.rn.f32x2).
// Only 100/256 position-blocks are nonzero -> 2.2x fewer MACs than dense.
// ---------------------------------------------------------------------------

#define BATCH 2048
#define TSTEPS 128
#define FEAT 84
#define BT (BATCH * TSTEPS)

typedef unsigned long long ull;

__device__ __align__(128) float g_W1[FEAT * 64];
__device__ __align__(128) float g_b1[64];
__device__ __align__(128) float g_S[1024 * 64];        // S[o][c]
__device__ __align__(128) float g_Q[64 * 4096];        // [k][j]; j = gate*2048 + pos*128 + co
__device__ __align__(128) float g_bias_if[4096];       // [gate*2048 + pos*128 + co]
__device__ __align__(128) float g_Wblk[9 * 128 * 128]; // [offset][ci][co]
__device__ __align__(128) float g_bias_o[2048];        // [pos*128 + co]
__device__ __align__(128) float g_bias_g[2048];
__device__ __align__(128) float g_enc[(size_t)BT * 64];
__device__ __align__(128) float g_h[2][(size_t)BATCH * 2048];
__device__ __align__(128) float g_c[(size_t)BATCH * 2048];
__device__ __align__(128) float g_hid[(size_t)BATCH * 128];

// ---------------- f32x2 helpers ----------------

__device__ __forceinline__ uint32_t smem_u32(const void* p) {
    uint32_t a;
    asm("{ .reg .u64 t; cvta.to.shared.u64 t, %1; cvt.u32.u64 %0, t; }" : "=r"(a) : "l"(p));
    return a;
}
__device__ __forceinline__ void lds_b2(ull& x, ull& y, uint32_t addr) {
    asm volatile("ld.shared.v2.u64 {%0,%1}, [%2];" : "=l"(x), "=l"(y) : "r"(addr));
}
__device__ __forceinline__ ull dup2(float b) {
    ull d; asm("mov.b64 %0, {%1,%1};" : "=l"(d) : "f"(b)); return d;
}
__device__ __forceinline__ void fma2(ull& d, ull a, ull b) {
    asm("fma.rn.f32x2 %0, %1, %2, %0;" : "+l"(d) : "l"(a), "l"(b));
}
__device__ __forceinline__ float xlo(ull v) { return __uint_as_float((uint32_t)v); }
__device__ __forceinline__ float xhi(ull v) { return __uint_as_float((uint32_t)(v >> 32)); }

// ---------------- weight prep kernels (cheap, run every launch) ----------------

__global__ void k_prep_w1(const float* __restrict__ cw, const float* __restrict__ cb,
                          const float* __restrict__ gam, const float* __restrict__ bet,
                          const float* __restrict__ mean, const float* __restrict__ var) {
    int i = blockIdx.x * blockDim.x + threadIdx.x;
    if (i >= FEAT * 64) return;
    int f = i / 64, c = i % 64;
    float s = gam[c] * rsqrtf(var[c] + 1e-5f);
    g_W1[f * 64 + c] = cw[c * (FEAT * 3) + f * 3 + 1] * s;   // center tap only
    if (f == 0) g_b1[c] = (cb[c] - mean[c]) * s + bet[c];
}

__global__ void k_S(const float* __restrict__ lin_w) {
    int idx = blockIdx.x * blockDim.x + threadIdx.x;
    if (idx >= 1024 * 64) return;
    int o = idx >> 6, c = idx & 63;
    float s = 0.f;
#pragma unroll
    for (int j = 0; j < 16; j++) s += lin_w[(size_t)o * 1024 + (c << 4) + j];
    g_S[idx] = s;
}

// Qi/Qf folded through Linear; columns stored position-major: pos*128 + co.
__global__ void k_buildQ(const float* __restrict__ cell_w, const float* __restrict__ cell_b,
                         const float* __restrict__ lin_b) {
    int idx = blockIdx.x * blockDim.x + threadIdx.x;
    if (idx >= 4096 * 64) return;
    int j = idx / 64, c = idx % 64;
    int gate = j / 2048;               // 0 = i, 1 = f(x part)
    int jj = j % 2048;
    int co = jj / 16, pos = jj % 16;
    int py = pos / 4, px = pos % 4;
    int wco = (gate == 0) ? co : 128 + co;
    int nci = (gate == 0) ? 48 : 16;
    float acc = 0.f, bacc = 0.f;
    for (int ci = 0; ci < nci; ci++) {
        int xch = (gate == 0) ? ci : 48 + ci;
        for (int ky = 0; ky < 3; ky++) {
            int qy = py + ky - 1; if (qy < 0 || qy > 3) continue;
            for (int kx = 0; kx < 3; kx++) {
                int qx = px + kx - 1; if (qx < 0 || qx > 3) continue;
                float w = cell_w[(size_t)wco * 432 + ci * 9 + ky * 3 + kx];
                int o = xch * 16 + qy * 4 + qx;
                acc += w * g_S[o * 64 + c];
                if (c == 0) bacc += w * lin_b[o];
            }
        }
    }
    int newj = gate * 2048 + pos * 128 + co;
    g_Q[(size_t)c * 4096 + newj] = acc;
    if (c == 0) g_bias_if[newj] = cell_b[wco] + bacc;
}

// 9-offset dense weight blocks: Wblk[di][ci][co], ci = h channel (gate-sliced).
__global__ void k_buildWblk(const float* __restrict__ cell_w) {
    int idx = blockIdx.x * blockDim.x + threadIdx.x;
    if (idx >= 9 * 128 * 128) return;
    int co = idx & 127;
    int ci = (idx >> 7) & 127;
    int di = idx >> 14;
    int ky = di / 3, kx = di % 3;
    int wco, ig;
    if (ci < 32)      { wco = 128 + co; ig = 16 + ci; }   // gate f: h ch 0..31
    else if (ci < 80) { wco = 256 + co; ig = ci - 32; }   // gate o: h ch 32..79
    else              { wco = 384 + co; ig = ci - 80; }   // gate g: h ch 80..127
    g_Wblk[idx] = cell_w[(size_t)wco * 432 + ig * 9 + ky * 3 + kx];
}

__global__ void k_bias_og(const float* __restrict__ cell_b) {
    int idx = blockIdx.x * blockDim.x + threadIdx.x;
    if (idx >= 2048) return;
    int co = idx & 127;
    g_bias_o[idx] = cell_b[256 + co];
    g_bias_g[idx] = cell_b[384 + co];
}

// ---------------- encoder ----------------

__global__ void k_enc(const float* __restrict__ x) {
    __shared__ float sW[FEAT * 64];
    __shared__ float sb[64];
    __shared__ float sx[32][FEAT];
    int tid = threadIdx.x;
    for (int i = tid; i < FEAT * 64; i += 256) sW[i] = g_W1[i];
    if (tid < 64) sb[tid] = g_b1[tid];
    size_t row0 = (size_t)blockIdx.x * 32;
    for (int i = tid; i < 32 * FEAT; i += 256) {
        int r = i / FEAT, f = i % FEAT;
        sx[r][f] = x[(row0 + r) * FEAT + f];
    }
    __syncthreads();
    int c = tid & 63;
    int rg = tid >> 6;
    for (int rr = 0; rr < 8; rr++) {
        int r = rg * 8 + rr;
        float acc = sb[c];
#pragma unroll 4
        for (int f = 0; f < FEAT; f++) acc += sx[r][f] * sW[f * 64 + c];
        g_enc[(row0 + r) * 64 + c] = fmaxf(acc, 0.f);
    }
}

__global__ void k_zero() {
    size_t i = (size_t)blockIdx.x * blockDim.x + threadIdx.x;
    if (i < (size_t)BATCH * 2048) { g_h[0][i] = 0.f; g_c[i] = 0.f; }
}

// ---------------- recurrent step ----------------
// CTA: 64 batch rows x 128 channels at one output position p.
// Thread (tx 0..15, ty 0..15): rows 4ty..4ty+3, cols {4tx..4tx+3, 64+4tx..+3}
// acc[m*4+jp]: jp 0,1 -> col pairs (4tx,4tx+1),(4tx+2,4tx+3); jp 2,3 -> +64.

#define INNERB(ACC, BADDR)                                                          \
    do {                                                                            \
        _Pragma("unroll 4")                                                         \
        for (int k = 0; k < 16; k++) {                                              \
            float4 a = *(const float4*)&us[k][ty << 2];                             \
            ull A0 = dup2(a.x), A1 = dup2(a.y), A2 = dup2(a.z), A3 = dup2(a.w);     \
            ull b0, b1, b2, b3;                                                     \
            lds_b2(b0, b1, (BADDR) + k * 512);                                      \
            lds_b2(b2, b3, (BADDR) + k * 512 + 256);                                \
            fma2(ACC[0], A0, b0);  fma2(ACC[1], A0, b1);                            \
            fma2(ACC[2], A0, b2);  fma2(ACC[3], A0, b3);                            \
            fma2(ACC[4], A1, b0);  fma2(ACC[5], A1, b1);                            \
            fma2(ACC[6], A1, b2);  fma2(ACC[7], A1, b3);                            \
            fma2(ACC[8], A2, b0);  fma2(ACC[9], A2, b1);                            \
            fma2(ACC[10], A2, b2); fma2(ACC[11], A2, b3);                           \
            fma2(ACC[12], A3, b0); fma2(ACC[13], A3, b1);                           \
            fma2(ACC[14], A3, b2); fma2(ACC[15], A3, b3);                           \
        }                                                                           \
    } while (0)

__global__ void __launch_bounds__(256, 1) k_step(int t) {
    __shared__ float us[16][64];    // [k][b]
    __shared__ float ws[16][128];   // [k][co]
    __shared__ float ws2[16][128];  // second B (enc dual phase)
    const int tid = threadIdx.x;
    const int tx = tid & 15, ty = tid >> 4;
    const int bb = blockIdx.x << 6;
    const int p = blockIdx.y;                 // output position 0..15
    const int py = p >> 2, px = p & 3;
    const float* __restrict__ hin = g_h[t & 1];
    float* __restrict__ hout = g_h[(t & 1) ^ 1];
    const float* enc_t = g_enc + ((size_t)bb * TSTEPS + t) * 64;
    const float* hrow = hin + (size_t)bb * 2048;
    const uint32_t ws_b = smem_u32(ws), ws2_b = smem_u32(ws2);
    const uint32_t baddr = ws_b + tx * 16;
    const uint32_t baddr2 = ws2_b + tx * 16;

    ull acc_i[16], acc_f[16], acc_o[16], acc_g[16];
#pragma unroll
    for (int e = 0; e < 16; e++) { acc_i[e] = 0ull; acc_f[e] = 0ull; acc_o[e] = 0ull; acc_g[e] = 0ull; }

    const int lb = tid >> 2, lk4 = (tid & 3) << 2;   // A loader: row lb, k sub lk4
    const int wk = tid >> 4, wj8 = (tid & 15) << 3;  // B loader: k row wk, col wj8

    // ===== enc phase (dual B): K=64 -> acc_i, acc_f =====
    {
        const float* Ap = enc_t + (size_t)lb * (TSTEPS * 64) + lk4;
        const float* B1 = g_Q + (size_t)wk * 4096 + p * 128 + wj8;
        const float* B2 = B1 + 2048;
        float4 av = *(const float4*)Ap;
        float4 b1a = *(const float4*)B1;
        float4 b1b = *(const float4*)(B1 + 4);
        float4 b2a = *(const float4*)B2;
        float4 b2b = *(const float4*)(B2 + 4);
#pragma unroll
        for (int kt = 0; kt < 4; kt++) {
            __syncthreads();
            us[lk4 + 0][lb] = av.x; us[lk4 + 1][lb] = av.y;
            us[lk4 + 2][lb] = av.z; us[lk4 + 3][lb] = av.w;
            *(float4*)&ws[wk][wj8] = b1a;  *(float4*)&ws[wk][wj8 + 4] = b1b;
            *(float4*)&ws2[wk][wj8] = b2a; *(float4*)&ws2[wk][wj8 + 4] = b2b;
            __syncthreads();
            if (kt < 3) {
                av = *(const float4*)(Ap + (kt + 1) * 16);
                b1a = *(const float4*)(B1 + (size_t)(kt + 1) * 16 * 4096);
                b1b = *(const float4*)(B1 + (size_t)(kt + 1) * 16 * 4096 + 4);
                b2a = *(const float4*)(B2 + (size_t)(kt + 1) * 16 * 4096);
                b2b = *(const float4*)(B2 + (size_t)(kt + 1) * 16 * 4096 + 4);
            }
            INNERB(acc_i, baddr);
            INNERB(acc_f, baddr2);
        }
    }

    // ===== h phase: neighbor position blocks, K=128 each =====
#pragma unroll 1
    for (int di = 0; di < 9; di++) {
        int qy = py + di / 3 - 1, qx = px + di % 3 - 1;
        if ((unsigned)qy > 3u || (unsigned)qx > 3u) continue;
        int q = qy * 4 + qx;
        const float* Ap = hrow + q * 128 + (size_t)lb * 2048 + lk4;
        const float* Bp = g_Wblk + (size_t)di * 16384 + (size_t)wk * 128 + wj8;
        float4 av = *(const float4*)Ap;
        float4 ba = *(const float4*)Bp;
        float4 bbv = *(const float4*)(Bp + 4);
#pragma unroll
        for (int kt = 0; kt < 8; kt++) {
            __syncthreads();
            us[lk4 + 0][lb] = av.x; us[lk4 + 1][lb] = av.y;
            us[lk4 + 2][lb] = av.z; us[lk4 + 3][lb] = av.w;
            *(float4*)&ws[wk][wj8] = ba; *(float4*)&ws[wk][wj8 + 4] = bbv;
            __syncthreads();
            if (kt < 7) {
                av = *(const float4*)(Ap + (kt + 1) * 16);
                ba = *(const float4*)(Bp + (size_t)(kt + 1) * 16 * 128);
                bbv = *(const float4*)(Bp + (size_t)(kt + 1) * 16 * 128 + 4);
            }
            // ci 0..31 -> f, 32..79 -> o, 80..127 -> g (compile-time per kt)
            if (kt < 2)      { INNERB(acc_f, baddr); }
            else if (kt < 5) { INNERB(acc_o, baddr); }
            else             { INNERB(acc_g, baddr); }
        }
    }

    // ===== fused LSTM epilogue =====
#pragma unroll
    for (int m = 0; m < 4; m++) {
        int b = bb + (ty << 2) + m;
        size_t roff = (size_t)b * 2048 + p * 128;
#pragma unroll
        for (int g2 = 0; g2 < 2; g2++) {
            int colbase = g2 * 64 + (tx << 2);
            size_t off = roff + colbase;
            float4 cold = *(const float4*)(g_c + off);
            float cold4[4] = {cold.x, cold.y, cold.z, cold.w};
            float cn[4], hn[4];
#pragma unroll
            for (int e2 = 0; e2 < 4; e2++) {
                int jp = g2 * 2 + (e2 >> 1);
                int e = m * 4 + jp;
                bool hi = e2 & 1;
                int jn = p * 128 + colbase + e2;
                float pi = (hi ? xhi(acc_i[e]) : xlo(acc_i[e])) + g_bias_if[jn];
                float pf = (hi ? xhi(acc_f[e]) : xlo(acc_f[e])) + g_bias_if[2048 + jn];
                float po = (hi ? xhi(acc_o[e]) : xlo(acc_o[e])) + g_bias_o[jn];
                float pg = (hi ? xhi(acc_g[e]) : xlo(acc_g[e])) + g_bias_g[jn];
                float si = 1.f / (1.f + __expf(-pi));
                float sf = 1.f / (1.f + __expf(-pf));
                float so = 1.f / (1.f + __expf(-po));
                float tg = 2.f / (1.f + __expf(-2.f * pg)) - 1.f;
                float c2 = sf * cold4[e2] + si * tg;
                cn[e2] = c2;
                float tc = 2.f / (1.f + __expf(-2.f * c2)) - 1.f;
                hn[e2] = so * tc;
            }
            *(float4*)(g_c + off)  = make_float4(cn[0], cn[1], cn[2], cn[3]);
            *(float4*)(hout + off) = make_float4(hn[0], hn[1], hn[2], hn[3]);
        }
    }
}

// ---------------- classifier ----------------
// h columns are position-major (pos*128+co); original feature index = co*16+pos.

__global__ void k_cls1(const float* __restrict__ w, const float* __restrict__ bias) {
    __shared__ float sf[16][64];
    __shared__ float sw[64][129];
    const float* hptr = g_h[0];
    int tid = threadIdx.x;
    int b0 = blockIdx.x * 16;
    float acc[16];
#pragma unroll
    for (int r = 0; r < 16; r++) acc[r] = 0.f;
    for (int k0 = 0; k0 < 2048; k0 += 64) {
        __syncthreads();
        for (int i = tid; i < 16 * 64; i += 128) {
            int r = i / 64, kl = i % 64;
            sf[r][kl] = hptr[(size_t)(b0 + r) * 2048 + k0 + kl];
        }
        {
            int kl = tid % 64, og = tid / 64;
            int kg = k0 + kl;
            int worig = (kg & 127) * 16 + (kg >> 7);   // pos-major -> channel-major
            for (int o = og; o < 128; o += 2)
                sw[kl][o] = w[(size_t)o * 2048 + worig];
        }
        __syncthreads();
        for (int kl = 0; kl < 64; kl++) {
            float wv = sw[kl][tid];
#pragma unroll
            for (int r = 0; r < 16; r++) acc[r] += sf[r][kl] * wv;
        }
    }
    for (int r = 0; r < 16; r++)
        g_hid[(size_t)(b0 + r) * 128 + tid] = fmaxf(acc[r] + bias[tid], 0.f);
}

__global__ void k_cls2(const float* __restrict__ w, const float* __restrict__ b,
                       float* __restrict__ out) {
    int bi = blockIdx.x * blockDim.x + threadIdx.x;
    if (bi >= BATCH) return;
    float a0 = b[0], a1 = b[1];
    for (int k = 0; k < 128; k++) {
        float h = g_hid[(size_t)bi * 128 + k];
        a0 += h * w[k];
        a1 += h * w[128 + k];
    }
    out[bi * 2 + 0] = a0;
    out[bi * 2 + 1] = a1;
}

// ---------------- launch ----------------

extern "C" void kernel_launch(void* const* d_in, const int* in_sizes, int n_in,
                              void* d_out, int out_size) {
    const float* x        = (const float*)d_in[0];
    const float* conv1d_w = (const float*)d_in[1];
    const float* conv1d_b = (const float*)d_in[2];
    const float* bn_gamma = (const float*)d_in[3];
    const float* bn_beta  = (const float*)d_in[4];
    const float* bn_mean  = (const float*)d_in[5];
    const float* bn_var   = (const float*)d_in[6];
    const float* lin_w    = (const float*)d_in[7];
    const float* lin_b    = (const float*)d_in[8];
    const float* cell_w   = (const float*)d_in[9];
    const float* cell_b   = (const float*)d_in[10];
    const float* cls1_w   = (const float*)d_in[11];
    const float* cls1_b   = (const float*)d_in[12];
    const float* cls2_w   = (const float*)d_in[13];
    const float* cls2_b   = (const float*)d_in[14];
    float* out = (float*)d_out;

    k_prep_w1<<<(FEAT * 64 + 255) / 256, 256>>>(conv1d_w, conv1d_b, bn_gamma, bn_beta, bn_mean, bn_var);
    k_S<<<(1024 * 64 + 255) / 256, 256>>>(lin_w);
    k_buildQ<<<(4096 * 64 + 255) / 256, 256>>>(cell_w, cell_b, lin_b);
    k_buildWblk<<<(9 * 128 * 128 + 255) / 256, 256>>>(cell_w);
    k_bias_og<<<(2048 + 255) / 256, 256>>>(cell_b);
    k_enc<<<BT / 32, 256>>>(x);
    k_zero<<<(int)(((size_t)BATCH * 2048 + 255) / 256), 256>>>();

    for (int t = 0; t < TSTEPS; t++)
        k_step<<<dim3(BATCH / 64, 16), 256>>>(t);

    k_cls1<<<BATCH / 16, 128>>>(cls1_w, cls1_b);
    k_cls2<<<(BATCH + 127) / 128, 128>>>(cls2_w, cls2_b, out);
}